// round 3
// baseline (speedup 1.0000x reference)
#include <cuda_runtime.h>
#include <cstdint>

// WeightedEmbeddingBag: B=4096, N=200, M=26, VOCAB=100000, D=128
// Inputs (metadata order) — NOTE: JAX x64 is disabled by default, so the
// "int64" tensors in the reference are actually materialized as int32:
//   d_in[0] input              int32  [B, N]
//   d_in[1] per_sample_weights fp32   [B, N]
//   d_in[2] offsets            int32  [B, M]  (sorted per row, values in [0, N))
//   d_in[3] emb_weight         fp32   [VOCAB, D]
// Output: fp32 [B, M, D]
//
// Semantics (from the reference cumsum/gather):
//   padded_offsets = [0, offsets+1]
//   out[b,m,:] = sum_{n = padded_offsets[m]}^{padded_offsets[m+1]-1} w[b,n] * emb[id[b,n]]
// Reproduced exactly by a running accumulator with snapshots at n == offsets[b,m].

#define BB 4096
#define NN 200
#define MM 26
#define DD 128
#define WARPS_PER_CTA 4

__global__ __launch_bounds__(32 * WARPS_PER_CTA)
void ebag_kernel(const int*    __restrict__ input,
                 const float*  __restrict__ psw,
                 const int*    __restrict__ offsets,
                 const float4* __restrict__ emb4,   // [VOCAB, 32] float4
                 float4*       __restrict__ out4)   // [B, M, 32] float4
{
    const int wid  = threadIdx.x >> 5;
    const int lane = threadIdx.x & 31;
    const int b    = blockIdx.x * WARPS_PER_CTA + wid;
    if (b >= BB) return;

    __shared__ int s_off[WARPS_PER_CTA][32];
    if (lane < MM)
        s_off[wid][lane] = offsets[(size_t)b * MM + lane];
    __syncwarp();

    const int*   in_b = input + (size_t)b * NN;
    const float* w_b  = psw   + (size_t)b * NN;
    float4*      o_b  = out4  + (size_t)b * MM * (DD / 4);

    // Last n we must consume (inclusive). Defensive clamp: if the offsets
    // dtype assumption is ever wrong, fail correctness cleanly, not with an
    // illegal access.
    int nmax = s_off[wid][MM - 1];
    if (nmax > NN - 1) nmax = NN - 1;
    if (nmax < 0)      nmax = 0;

    float4 acc  = make_float4(0.f, 0.f, 0.f, 0.f);
    float4 snap = make_float4(0.f, 0.f, 0.f, 0.f);
    int m   = 0;
    int cur = s_off[wid][0];

    // Software prefetch depth 2: the 512B embedding-row gather for n+1 is issued
    // before the FMA of row n, so the L2 gather latency (~234 cyc) is off the
    // accumulate critical path.
    int    id0 = in_b[0];
    float  w0  = w_b[0];
    float4 v0  = emb4[(size_t)id0 * 32 + lane];

    for (int n = 0; n <= nmax; n++) {
        const int np = (n + 1 <= nmax) ? (n + 1) : nmax;   // harmless re-load on last iter
        const int    id1 = in_b[np];
        const float  w1  = w_b[np];
        const float4 v1  = emb4[(size_t)id1 * 32 + lane];

        acc.x = fmaf(w0, v0.x, acc.x);
        acc.y = fmaf(w0, v0.y, acc.y);
        acc.z = fmaf(w0, v0.z, acc.z);
        acc.w = fmaf(w0, v0.w, acc.w);

        // Emit every segment ending at this n (duplicated offsets -> empty
        // segments -> exact zeros, matching the cumsum-difference reference).
        while (cur == n) {
            float4 r = make_float4(acc.x - snap.x, acc.y - snap.y,
                                   acc.z - snap.z, acc.w - snap.w);
            o_b[m * (DD / 4) + lane] = r;
            snap = acc;
            m++;
            cur = (m < MM) ? s_off[wid][m] : -1;
        }

        v0 = v1;
        w0 = w1;
    }
}

extern "C" void kernel_launch(void* const* d_in, const int* in_sizes, int n_in,
                              void* d_out, int out_size)
{
    const int*    input   = (const int*)   d_in[0];
    const float*  psw     = (const float*) d_in[1];
    const int*    offsets = (const int*)   d_in[2];
    const float4* emb4    = (const float4*)d_in[3];
    float4*       out4    = (float4*)d_out;

    dim3 grid(BB / WARPS_PER_CTA);
    dim3 block(32 * WARPS_PER_CTA);
    ebag_kernel<<<grid, block>>>(input, psw, offsets, emb4, out4);
}